// round 10
// baseline (speedup 1.0000x reference)
#include <cuda_runtime.h>
#include <math.h>

#define N_ENT   14541
#define EMB_DIM 768
#define EMB_V4  192            // EMB_DIM / 4
#define TOP_K   1000
#define NEG_T   5
#define BS      128
#define MARGIN  0.5f

#define KSLICES 4
#define KSEG    (TOP_K / KSLICES)      // 250
#define A_BLKS  (BS * KSLICES)         // 512 alpha partial blocks
#define ROW0    A_BLKS                 // first row block
#define EPI0    (A_BLKS + N_ENT)       // first epilogue block
#define GRID_SZ (EPI0 + BS)            // 15181
#define GATE1   A_BLKS                 // psum/psq ready
#define GATE2   (A_BLKS + N_ENT)       // simi_mean ready

// Scratch (no cudaMalloc allowed; zero-initialized at module load,
// counters are reset by the last epilogue block each run -> replay-safe)
__device__ float  g_simi_mean[N_ENT];
__device__ float4 g_psum[A_BLKS * EMB_V4];
__device__ float4 g_psq [A_BLKS * EMB_V4];
__device__ unsigned int g_done;
__device__ unsigned int g_pb_done;

// ---------------------------------------------------------------------------
__device__ __forceinline__ float block_reduce_sum(float v, float* sh) {
    #pragma unroll
    for (int o = 16; o > 0; o >>= 1) v += __shfl_down_sync(0xffffffffu, v, o);
    int wid = threadIdx.x >> 5;
    int lid = threadIdx.x & 31;
    if (lid == 0) sh[wid] = v;
    __syncthreads();
    int nw = blockDim.x >> 5;
    if (wid == 0) {
        v = (lid < nw) ? sh[lid] : 0.0f;
        #pragma unroll
        for (int o = 16; o > 0; o >>= 1) v += __shfl_down_sync(0xffffffffu, v, o);
    }
    return v;
}

__device__ __forceinline__ unsigned int poll_counter() {
    unsigned int v;
    asm volatile("ld.global.cg.u32 %0, [%1];" : "=r"(v) : "l"(&g_done));
    return v;
}
__device__ __forceinline__ float ldcg_f(const float* p) {
    float v;
    asm volatile("ld.global.cg.f32 %0, [%1];" : "=f"(v) : "l"(p));
    return v;
}
__device__ __forceinline__ float4 ldcg_f4(const float4* p) {
    float4 v;
    asm volatile("ld.global.cg.v4.f32 {%0,%1,%2,%3}, [%4];"
                 : "=f"(v.x), "=f"(v.y), "=f"(v.z), "=f"(v.w) : "l"(p));
    return v;
}

// Gate: thread 0 spins until g_done >= target, then block-wide release.
__device__ __forceinline__ void gate_wait(unsigned int target, int tid) {
    if (tid == 0) {
        while (poll_counter() < target) __nanosleep(128);
        __threadfence();
    }
    __syncthreads();
}

// ---------------------------------------------------------------------------
// ONE kernel, three roles by blockIdx:
//   [0, A_BLKS):        alpha Phase A partials (emb-std gather, front burst)
//   [ROW0, EPI0):       per-row mean of simi (__ldcs streaming, DRAM-bound)
//   [EPI0, GRID_SZ):    epilogue (per-sample): pre-stages score features while
//                       rows finish, gates on completion counters, gathers
//                       simi means, sigmoid + margin loss (atomicAdd).
// ---------------------------------------------------------------------------
__global__ __launch_bounds__(256)
void mega_kernel(const float* __restrict__ simi,
                 const int*   __restrict__ ent_idx,
                 const float* __restrict__ emb,
                 const float* __restrict__ stelp_scores,
                 const float* __restrict__ rotate_scores,
                 const float* __restrict__ proj_w,
                 const float* __restrict__ proj_b,
                 const float* __restrict__ pos_s,
                 const float* __restrict__ pos_r,
                 const float* __restrict__ neg_s,
                 const float* __restrict__ neg_r,
                 float* __restrict__ out) {
    __shared__ int   s_idx[KSEG];
    __shared__ float sh[8];
    const int tid = threadIdx.x;
    const int bid = blockIdx.x;

    if (bid < A_BLKS) {
        // ================= alpha Phase A partial =================
        const int b     = bid >> 2;
        const int slice = bid & 3;
        const int k0    = slice * KSEG;

        for (int k = tid; k < KSEG; k += 256)
            s_idx[k] = ent_idx[b * TOP_K + k0 + k];
        __syncthreads();

        if (tid < EMB_V4) {
            const float4* __restrict__ emb4 = (const float4*)emb;
            float s0 = 0.f, s1 = 0.f, s2 = 0.f, s3 = 0.f;
            float q0 = 0.f, q1 = 0.f, q2 = 0.f, q3 = 0.f;
            #pragma unroll 10
            for (int k = 0; k < KSEG; k++) {
                float4 v = __ldg(emb4 + (size_t)s_idx[k] * EMB_V4 + tid);
                s0 += v.x; s1 += v.y; s2 += v.z; s3 += v.w;
                q0 = fmaf(v.x, v.x, q0); q1 = fmaf(v.y, v.y, q1);
                q2 = fmaf(v.z, v.z, q2); q3 = fmaf(v.w, v.w, q3);
            }
            g_psum[bid * EMB_V4 + tid] = make_float4(s0, s1, s2, s3);
            g_psq [bid * EMB_V4 + tid] = make_float4(q0, q1, q2, q3);
        }
        __syncthreads();
        if (tid == 0) { __threadfence(); atomicAdd(&g_done, 1u); }

    } else if (bid < EPI0) {
        // ================= row mean (streaming .cs loads) =================
        const int r = bid - ROW0;
        if (r == 0 && tid == 0) out[0] = 0.0f;   // init for epilogue atomics

        const size_t e0 = (size_t)r * N_ENT;
        const size_t e1 = e0 + N_ENT;
        const size_t a0 = (e0 + 3) & ~(size_t)3;
        const size_t a1 = e1 & ~(size_t)3;

        float s = 0.0f;
        for (size_t e = e0 + tid; e < a0; e += 256) s += __ldcs(simi + e);
        for (size_t e = a1 + tid; e < e1; e += 256) s += __ldcs(simi + e);

        const float4* __restrict__ v4 = (const float4*)(simi + a0);
        const int nv = (int)((a1 - a0) >> 2);
        float4 a = make_float4(0.f, 0.f, 0.f, 0.f);
        #pragma unroll 4
        for (int i = tid; i < nv; i += 256) {
            float4 x = __ldcs(v4 + i);
            a.x += x.x; a.y += x.y; a.z += x.z; a.w += x.w;
        }
        s += (a.x + a.y) + (a.z + a.w);
        s = block_reduce_sum(s, sh);
        if (tid == 0) {
            g_simi_mean[r] = s * (1.0f / (float)N_ENT);
            __threadfence();
            atomicAdd(&g_done, 1u);
        }

    } else {
        // ================= epilogue: per-sample alpha + loss =================
        const int b = bid - EPI0;

        // ---- pre-gate: stage everything independent of row means ----
        const float* wS  = proj_w + EMB_DIM;
        const float* wD  = proj_w + EMB_DIM + TOP_K;
        const float* wA  = proj_w + EMB_DIM + 2 * TOP_K;
        const float* wSt = proj_w + EMB_DIM + 3 * TOP_K;
        const float* wR  = proj_w + EMB_DIM + 4 * TOP_K;

        int   ixs[4];
        float wSv[4];
        float acc = 0.0f;
        #pragma unroll
        for (int i = 0; i < 4; i++) {
            int k = i * 256 + tid;
            if (k < TOP_K) {
                ixs[i] = ent_idx[b * TOP_K + k];
                wSv[i] = wS[k];
                float ss = stelp_scores[b * TOP_K + k];
                float rr = rotate_scores[b * TOP_K + k];
                acc = fmaf(wD[k],  fabsf(rr - ss), acc);
                acc = fmaf(wA[k],  ss + rr,        acc);
                acc = fmaf(wSt[k], ss,             acc);
                acc = fmaf(wR[k],  rr,             acc);
            } else { ixs[i] = 0; wSv[i] = 0.0f; }
        }

        // ---- gate 1: psum/psq partials ready (passes ~immediately) ----
        gate_wait(GATE1, tid);
        if (tid < EMB_V4) {
            float4 S = make_float4(0.f, 0.f, 0.f, 0.f);
            float4 Q = make_float4(0.f, 0.f, 0.f, 0.f);
            #pragma unroll
            for (int s = 0; s < KSLICES; s++) {
                int pb = (b << 2) + s;
                float4 ps = ldcg_f4(&g_psum[pb * EMB_V4 + tid]);
                float4 pq = ldcg_f4(&g_psq [pb * EMB_V4 + tid]);
                S.x += ps.x; S.y += ps.y; S.z += ps.z; S.w += ps.w;
                Q.x += pq.x; Q.y += pq.y; Q.z += pq.z; Q.w += pq.w;
            }
            const float invK  = 1.0f / (float)TOP_K;
            const float invK1 = 1.0f / (float)(TOP_K - 1);
            float ss[4] = {S.x, S.y, S.z, S.w};
            float qq[4] = {Q.x, Q.y, Q.z, Q.w};
            #pragma unroll
            for (int c = 0; c < 4; c++) {
                float mean = ss[c] * invK;
                float var  = fmaxf((qq[c] - ss[c] * mean) * invK1, 0.0f);
                acc = fmaf(sqrtf(var), __ldg(proj_w + 4 * tid + c), acc);
            }
        }

        // ---- gate 2: all row means ready; only the simi gather remains ----
        gate_wait(GATE2, tid);
        #pragma unroll
        for (int i = 0; i < 4; i++)
            acc = fmaf(wSv[i], ldcg_f(&g_simi_mean[ixs[i]]), acc);

        float total = block_reduce_sum(acc, sh);
        if (tid == 0) {
            float z = total + proj_b[0];
            float a = 1.0f / (1.0f + __expf(-z));
            float pe = a * pos_s[b] + (1.0f - a) * pos_r[b];
            float lsum = 0.0f;
            #pragma unroll
            for (int j = 0; j < NEG_T; j++) {
                float ne = a * neg_s[b * NEG_T + j] + (1.0f - a) * neg_r[b * NEG_T + j];
                lsum += fmaxf(MARGIN - pe + ne, 0.0f);
            }
            atomicAdd(out, lsum * (1.0f / (float)(BS * NEG_T)));
            // last epilogue block resets the counters for graph replay
            unsigned int p = atomicAdd(&g_pb_done, 1u);
            if (p == (unsigned int)(BS - 1)) {
                g_done = 0u;
                g_pb_done = 0u;
            }
        }
    }
}

// ---------------------------------------------------------------------------
extern "C" void kernel_launch(void* const* d_in, const int* in_sizes, int n_in,
                              void* d_out, int out_size) {
    const float* pos_stelp  = (const float*)d_in[0];
    const float* pos_rotate = (const float*)d_in[1];
    const int*   ent_idx    = (const int*)  d_in[2];
    const float* neg_stelp  = (const float*)d_in[3];
    const float* neg_rotate = (const float*)d_in[4];
    const float* stelp_sc   = (const float*)d_in[5];
    const float* rotate_sc  = (const float*)d_in[6];
    const float* ent_emb    = (const float*)d_in[7];
    const float* simi_mtx   = (const float*)d_in[8];
    const float* proj_w     = (const float*)d_in[9];
    const float* proj_b     = (const float*)d_in[10];
    float* out = (float*)d_out;

    mega_kernel<<<GRID_SZ, 256>>>(simi_mtx, ent_idx, ent_emb,
                                  stelp_sc, rotate_sc, proj_w, proj_b,
                                  pos_stelp, pos_rotate, neg_stelp, neg_rotate,
                                  out);
}

// round 11
// speedup vs baseline: 1.0702x; 1.0702x over previous
#include <cuda_runtime.h>
#include <math.h>

#define N_ENT   14541
#define EMB_DIM 768
#define EMB_V4  192            // EMB_DIM / 4
#define TOP_K   1000
#define NEG_T   5
#define BS      128
#define MARGIN  0.5f

#define KSLICES 4
#define KSEG    (TOP_K / KSLICES)      // 250
#define A_BLKS  (BS * KSLICES)         // 512 alpha partial blocks

// Scratch (no cudaMalloc allowed)
__device__ float  g_simi_mean[N_ENT];
__device__ float4 g_psum[A_BLKS * EMB_V4];   // per (block, dim-group) partial sums
__device__ float4 g_psq [A_BLKS * EMB_V4];   // per (block, dim-group) partial sumsq
__device__ float  g_sacc[A_BLKS];            // per (b, slice) score-feature partial

// ---------------------------------------------------------------------------
// Block reduce: valid result in thread 0. Supports up to 1024 threads.
// ---------------------------------------------------------------------------
__device__ __forceinline__ float block_reduce_sum(float v, float* sh) {
    #pragma unroll
    for (int o = 16; o > 0; o >>= 1) v += __shfl_down_sync(0xffffffffu, v, o);
    int wid = threadIdx.x >> 5;
    int lid = threadIdx.x & 31;
    if (lid == 0) sh[wid] = v;
    __syncthreads();
    int nw = blockDim.x >> 5;
    if (wid == 0) {
        v = (lid < nw) ? sh[lid] : 0.0f;
        #pragma unroll
        for (int o = 16; o > 0; o >>= 1) v += __shfl_down_sync(0xffffffffu, v, o);
    }
    return v;
}

// ---------------------------------------------------------------------------
// Fused kernel 1 (alpha blocks FIRST as one short burst):
//   blocks [0, A_BLKS): alpha Phase A partials. Block (b, slice):
//       (1) gathers emb rows for its 250-k segment -> float4 sum/sumsq
//           partials (raw, no atomics, deterministic);
//       (2) computes the 4 row-mean-independent score-feature groups
//           (|r-s|, r+s, s, r) dotted with their weights -> g_sacc[bid].
//   blocks [A_BLKS, A_BLKS+N_ENT): per-row mean of simi_score_mtx
//       (DRAM-bound, __ldcs streaming so the emb table stays L2-resident).
// Block A_BLKS also zeroes out[0] for the atomic loss accumulation in k2.
// ---------------------------------------------------------------------------
__global__ __launch_bounds__(256)
void fused_kernel(const float* __restrict__ simi,
                  const int*   __restrict__ ent_idx,
                  const float* __restrict__ emb,
                  const float* __restrict__ stelp_scores,
                  const float* __restrict__ rotate_scores,
                  const float* __restrict__ proj_w,
                  float* __restrict__ out) {
    __shared__ int   s_idx[KSEG];
    __shared__ float sh[8];
    const int tid = threadIdx.x;

    if (blockIdx.x < A_BLKS) {
        // ================= alpha Phase A partial =================
        const int b     = blockIdx.x >> 2;       // sample
        const int slice = blockIdx.x & 3;        // k-slice
        const int k0    = slice * KSEG;

        for (int k = tid; k < KSEG; k += 256)
            s_idx[k] = ent_idx[b * TOP_K + k0 + k];
        __syncthreads();

        // ---- score-feature partial (independent of row means) ----
        const float* wD  = proj_w + EMB_DIM + TOP_K;        // |rot - stelp|
        const float* wA  = proj_w + EMB_DIM + 2 * TOP_K;    // stelp + rot
        const float* wSt = proj_w + EMB_DIM + 3 * TOP_K;    // stelp
        const float* wR  = proj_w + EMB_DIM + 4 * TOP_K;    // rot
        float sacc = 0.0f;
        for (int k = tid; k < KSEG; k += 256) {
            const int kk = k0 + k;
            float ss = stelp_scores[b * TOP_K + kk];
            float rr = rotate_scores[b * TOP_K + kk];
            sacc = fmaf(wD[kk],  fabsf(rr - ss), sacc);
            sacc = fmaf(wA[kk],  ss + rr,        sacc);
            sacc = fmaf(wSt[kk], ss,             sacc);
            sacc = fmaf(wR[kk],  rr,             sacc);
        }

        // ---- emb gather: sum/sumsq per 4-dim group ----
        if (tid < EMB_V4) {
            // Thread tid owns dims [4*tid, 4*tid+4). A warp = 32 consecutive
            // float4s of the SAME row -> fully coalesced 512B bursts.
            const float4* __restrict__ emb4 = (const float4*)emb;
            float s0 = 0.f, s1 = 0.f, s2 = 0.f, s3 = 0.f;
            float q0 = 0.f, q1 = 0.f, q2 = 0.f, q3 = 0.f;
            #pragma unroll 10
            for (int k = 0; k < KSEG; k++) {
                float4 v = __ldg(emb4 + (size_t)s_idx[k] * EMB_V4 + tid);
                s0 += v.x; s1 += v.y; s2 += v.z; s3 += v.w;
                q0 = fmaf(v.x, v.x, q0); q1 = fmaf(v.y, v.y, q1);
                q2 = fmaf(v.z, v.z, q2); q3 = fmaf(v.w, v.w, q3);
            }
            g_psum[blockIdx.x * EMB_V4 + tid] = make_float4(s0, s1, s2, s3);
            g_psq [blockIdx.x * EMB_V4 + tid] = make_float4(q0, q1, q2, q3);
        }

        float stot = block_reduce_sum(sacc, sh);
        if (tid == 0) g_sacc[blockIdx.x] = stot;

    } else {
        // ================= row mean (streaming .cs loads) =================
        const int r = blockIdx.x - A_BLKS;
        if (r == 0 && tid == 0) out[0] = 0.0f;   // init for k2's atomic loss

        const size_t e0 = (size_t)r * N_ENT;
        const size_t e1 = e0 + N_ENT;
        const size_t a0 = (e0 + 3) & ~(size_t)3;   // first 16B-aligned element
        const size_t a1 = e1 & ~(size_t)3;

        float s = 0.0f;
        for (size_t e = e0 + tid; e < a0; e += 256) s += __ldcs(simi + e);
        for (size_t e = a1 + tid; e < e1; e += 256) s += __ldcs(simi + e);

        const float4* __restrict__ v4 = (const float4*)(simi + a0);
        const int nv = (int)((a1 - a0) >> 2);
        float4 a = make_float4(0.f, 0.f, 0.f, 0.f);
        #pragma unroll 4
        for (int i = tid; i < nv; i += 256) {
            float4 x = __ldcs(v4 + i);
            a.x += x.x; a.y += x.y; a.z += x.z; a.w += x.w;
        }
        s += (a.x + a.y) + (a.z + a.w);
        s = block_reduce_sum(s, sh);
        if (tid == 0) g_simi_mean[r] = s * (1.0f / (float)N_ENT);
    }
}

// ---------------------------------------------------------------------------
// Kernel 2: combine Phase-A partials (std * w) + wS*simi_mean gather +
// score-feature partials + sigmoid + this sample's margin-loss contribution
// (atomicAdd into out[0], zeroed by k1).
// One block of 1024 threads per sample, one k per thread.
// ---------------------------------------------------------------------------
__global__ __launch_bounds__(1024)
void phaseB_kernel(const int*   __restrict__ ent_idx,
                   const float* __restrict__ proj_w,
                   const float* __restrict__ proj_b,
                   const float* __restrict__ pos_s,
                   const float* __restrict__ pos_r,
                   const float* __restrict__ neg_s,
                   const float* __restrict__ neg_r,
                   float* __restrict__ out) {
    __shared__ float sh[32];
    const int b   = blockIdx.x;
    const int tid = threadIdx.x;

    float acc = 0.0f;

    // ---- wS * simi_mean gather: one k per thread ----
    if (tid < TOP_K) {
        const float* wS = proj_w + EMB_DIM;
        int ix = ent_idx[b * TOP_K + tid];
        acc = fmaf(wS[tid], g_simi_mean[ix], acc);
    }

    // ---- combine the 4 k-slice partials, compute std(ddof=1) dot w ----
    if (tid < EMB_V4) {
        float4 S = make_float4(0.f, 0.f, 0.f, 0.f);
        float4 Q = make_float4(0.f, 0.f, 0.f, 0.f);
        #pragma unroll
        for (int s = 0; s < KSLICES; s++) {
            int pb = (b << 2) + s;
            float4 ps = g_psum[pb * EMB_V4 + tid];
            float4 pq = g_psq [pb * EMB_V4 + tid];
            S.x += ps.x; S.y += ps.y; S.z += ps.z; S.w += ps.w;
            Q.x += pq.x; Q.y += pq.y; Q.z += pq.z; Q.w += pq.w;
        }
        const float invK  = 1.0f / (float)TOP_K;
        const float invK1 = 1.0f / (float)(TOP_K - 1);
        float ss[4] = {S.x, S.y, S.z, S.w};
        float qq[4] = {Q.x, Q.y, Q.z, Q.w};
        #pragma unroll
        for (int c = 0; c < 4; c++) {
            float mean = ss[c] * invK;
            float var  = fmaxf((qq[c] - ss[c] * mean) * invK1, 0.0f);
            acc = fmaf(sqrtf(var), __ldg(proj_w + 4 * tid + c), acc);
        }
    }

    // ---- score-feature partials from k1 ----
    if (tid >= 1020) acc += g_sacc[(b << 2) + (tid - 1020)];

    float total = block_reduce_sum(acc, sh);

    // ---- sigmoid + this sample's loss contribution ----
    if (tid == 0) {
        float z = total + proj_b[0];
        float a = 1.0f / (1.0f + __expf(-z));
        float pe = a * pos_s[b] + (1.0f - a) * pos_r[b];
        float lsum = 0.0f;
        #pragma unroll
        for (int j = 0; j < NEG_T; j++) {
            float ne = a * neg_s[b * NEG_T + j] + (1.0f - a) * neg_r[b * NEG_T + j];
            lsum += fmaxf(MARGIN - pe + ne, 0.0f);
        }
        atomicAdd(out, lsum * (1.0f / (float)(BS * NEG_T)));
    }
}

// ---------------------------------------------------------------------------
extern "C" void kernel_launch(void* const* d_in, const int* in_sizes, int n_in,
                              void* d_out, int out_size) {
    const float* pos_stelp  = (const float*)d_in[0];
    const float* pos_rotate = (const float*)d_in[1];
    const int*   ent_idx    = (const int*)  d_in[2];
    const float* neg_stelp  = (const float*)d_in[3];
    const float* neg_rotate = (const float*)d_in[4];
    const float* stelp_sc   = (const float*)d_in[5];
    const float* rotate_sc  = (const float*)d_in[6];
    const float* ent_emb    = (const float*)d_in[7];
    const float* simi_mtx   = (const float*)d_in[8];
    const float* proj_w     = (const float*)d_in[9];
    const float* proj_b     = (const float*)d_in[10];
    float* out = (float*)d_out;

    fused_kernel<<<A_BLKS + N_ENT, 256>>>(simi_mtx, ent_idx, ent_emb,
                                          stelp_sc, rotate_sc, proj_w, out);
    phaseB_kernel<<<BS, 1024>>>(ent_idx, proj_w, proj_b,
                                pos_stelp, pos_rotate, neg_stelp, neg_rotate,
                                out);
}

// round 12
// speedup vs baseline: 1.0735x; 1.0031x over previous
#include <cuda_runtime.h>
#include <math.h>

#define N_ENT   14541
#define EMB_DIM 768
#define EMB_V4  192            // EMB_DIM / 4
#define TOP_K   1000
#define NEG_T   5
#define BS      128
#define MARGIN  0.5f

#define KSLICES 4
#define KSEG    (TOP_K / KSLICES)      // 250
#define A_BLKS  (BS * KSLICES)         // 512 alpha partial blocks

// Scratch (no cudaMalloc allowed)
__device__ float  g_simi_mean[N_ENT];
__device__ float4 g_psum[A_BLKS * EMB_V4];   // per (block, dim-group) partial sums
__device__ float4 g_psq [A_BLKS * EMB_V4];   // per (block, dim-group) partial sumsq
__device__ float  g_sacc[A_BLKS];            // per (b, slice) score-feature partial

// ---------------------------------------------------------------------------
// PDL primitives
// ---------------------------------------------------------------------------
__device__ __forceinline__ void pdl_trigger() {
    asm volatile("griddepcontrol.launch_dependents;");
}
__device__ __forceinline__ void pdl_wait() {
    asm volatile("griddepcontrol.wait;" ::: "memory");
}

// ---------------------------------------------------------------------------
// Block reduce: valid result in thread 0. Supports up to 1024 threads.
// ---------------------------------------------------------------------------
__device__ __forceinline__ float block_reduce_sum(float v, float* sh) {
    #pragma unroll
    for (int o = 16; o > 0; o >>= 1) v += __shfl_down_sync(0xffffffffu, v, o);
    int wid = threadIdx.x >> 5;
    int lid = threadIdx.x & 31;
    if (lid == 0) sh[wid] = v;
    __syncthreads();
    int nw = blockDim.x >> 5;
    if (wid == 0) {
        v = (lid < nw) ? sh[lid] : 0.0f;
        #pragma unroll
        for (int o = 16; o > 0; o >>= 1) v += __shfl_down_sync(0xffffffffu, v, o);
    }
    return v;
}

// ---------------------------------------------------------------------------
// Fused kernel 1 (alpha blocks FIRST as one short burst):
//   blocks [0, A_BLKS): alpha Phase A partials. Block (b, slice):
//       (1) gathers emb rows for its 250-k segment -> float4 sum/sumsq
//           partials (raw, no atomics, deterministic);
//       (2) computes the 4 row-mean-independent score-feature groups
//           (|r-s|, r+s, s, r) dotted with their weights -> g_sacc[bid].
//   blocks [A_BLKS, A_BLKS+N_ENT): per-row mean of simi_score_mtx
//       (DRAM-bound, __ldcs streaming so the emb table stays L2-resident).
// Every block triggers PDL as its LAST action so phaseB launches while the
// final wave drains (no occupancy theft during the DRAM stream).
// ---------------------------------------------------------------------------
__global__ __launch_bounds__(256)
void fused_kernel(const float* __restrict__ simi,
                  const int*   __restrict__ ent_idx,
                  const float* __restrict__ emb,
                  const float* __restrict__ stelp_scores,
                  const float* __restrict__ rotate_scores,
                  const float* __restrict__ proj_w,
                  float* __restrict__ out) {
    __shared__ int   s_idx[KSEG];
    __shared__ float sh[8];
    const int tid = threadIdx.x;

    if (blockIdx.x < A_BLKS) {
        // ================= alpha Phase A partial =================
        const int b     = blockIdx.x >> 2;       // sample
        const int slice = blockIdx.x & 3;        // k-slice
        const int k0    = slice * KSEG;

        for (int k = tid; k < KSEG; k += 256)
            s_idx[k] = ent_idx[b * TOP_K + k0 + k];
        __syncthreads();

        // ---- score-feature partial (independent of row means) ----
        const float* wD  = proj_w + EMB_DIM + TOP_K;        // |rot - stelp|
        const float* wA  = proj_w + EMB_DIM + 2 * TOP_K;    // stelp + rot
        const float* wSt = proj_w + EMB_DIM + 3 * TOP_K;    // stelp
        const float* wR  = proj_w + EMB_DIM + 4 * TOP_K;    // rot
        float sacc = 0.0f;
        for (int k = tid; k < KSEG; k += 256) {
            const int kk = k0 + k;
            float ss = stelp_scores[b * TOP_K + kk];
            float rr = rotate_scores[b * TOP_K + kk];
            sacc = fmaf(wD[kk],  fabsf(rr - ss), sacc);
            sacc = fmaf(wA[kk],  ss + rr,        sacc);
            sacc = fmaf(wSt[kk], ss,             sacc);
            sacc = fmaf(wR[kk],  rr,             sacc);
        }

        // ---- emb gather: sum/sumsq per 4-dim group ----
        if (tid < EMB_V4) {
            // Thread tid owns dims [4*tid, 4*tid+4). A warp = 32 consecutive
            // float4s of the SAME row -> fully coalesced 512B bursts.
            const float4* __restrict__ emb4 = (const float4*)emb;
            float s0 = 0.f, s1 = 0.f, s2 = 0.f, s3 = 0.f;
            float q0 = 0.f, q1 = 0.f, q2 = 0.f, q3 = 0.f;
            #pragma unroll 10
            for (int k = 0; k < KSEG; k++) {
                float4 v = __ldg(emb4 + (size_t)s_idx[k] * EMB_V4 + tid);
                s0 += v.x; s1 += v.y; s2 += v.z; s3 += v.w;
                q0 = fmaf(v.x, v.x, q0); q1 = fmaf(v.y, v.y, q1);
                q2 = fmaf(v.z, v.z, q2); q3 = fmaf(v.w, v.w, q3);
            }
            g_psum[blockIdx.x * EMB_V4 + tid] = make_float4(s0, s1, s2, s3);
            g_psq [blockIdx.x * EMB_V4 + tid] = make_float4(q0, q1, q2, q3);
        }

        float stot = block_reduce_sum(sacc, sh);
        if (tid == 0) g_sacc[blockIdx.x] = stot;

    } else {
        // ================= row mean (streaming .cs loads) =================
        const int r = blockIdx.x - A_BLKS;
        if (r == 0 && tid == 0) out[0] = 0.0f;   // init for k2's atomic loss

        const size_t e0 = (size_t)r * N_ENT;
        const size_t e1 = e0 + N_ENT;
        const size_t a0 = (e0 + 3) & ~(size_t)3;   // first 16B-aligned element
        const size_t a1 = e1 & ~(size_t)3;

        float s = 0.0f;
        for (size_t e = e0 + tid; e < a0; e += 256) s += __ldcs(simi + e);
        for (size_t e = a1 + tid; e < e1; e += 256) s += __ldcs(simi + e);

        const float4* __restrict__ v4 = (const float4*)(simi + a0);
        const int nv = (int)((a1 - a0) >> 2);
        float4 a = make_float4(0.f, 0.f, 0.f, 0.f);
        #pragma unroll 4
        for (int i = tid; i < nv; i += 256) {
            float4 x = __ldcs(v4 + i);
            a.x += x.x; a.y += x.y; a.z += x.z; a.w += x.w;
        }
        s += (a.x + a.y) + (a.z + a.w);
        s = block_reduce_sum(s, sh);
        if (tid == 0) g_simi_mean[r] = s * (1.0f / (float)N_ENT);
    }

    // Last action of every block: allow the dependent grid to launch.
    pdl_trigger();
}

// ---------------------------------------------------------------------------
// Kernel 2 (PDL secondary): prologue loads everything independent of the
// fused kernel's outputs, then griddepcontrol.wait, then only the short
// L2-hot dependent part (simi_mean gather + partial combines + loss).
// One block of 1024 threads per sample, one k per thread.
// ---------------------------------------------------------------------------
__global__ __launch_bounds__(1024)
void phaseB_kernel(const int*   __restrict__ ent_idx,
                   const float* __restrict__ proj_w,
                   const float* __restrict__ proj_b,
                   const float* __restrict__ pos_s,
                   const float* __restrict__ pos_r,
                   const float* __restrict__ neg_s,
                   const float* __restrict__ neg_r,
                   float* __restrict__ out) {
    __shared__ float sh[32];
    const int b   = blockIdx.x;
    const int tid = threadIdx.x;

    // ---- prologue (overlaps with fused drain): input-only loads ----
    int   ix  = 0;
    float wsv = 0.0f;
    if (tid < TOP_K) {
        ix  = ent_idx[b * TOP_K + tid];
        wsv = __ldg(proj_w + EMB_DIM + tid);       // wS[tid]
    }
    float wstd[4] = {0.f, 0.f, 0.f, 0.f};
    if (tid < EMB_V4) {
        #pragma unroll
        for (int c = 0; c < 4; c++) wstd[c] = __ldg(proj_w + 4 * tid + c);
    }
    float pb_bias = (tid == 0) ? __ldg(proj_b) : 0.0f;
    float psv = 0.f, prv = 0.f, nsv[NEG_T], nrv[NEG_T];
    if (tid == 0) {
        psv = pos_s[b]; prv = pos_r[b];
        #pragma unroll
        for (int j = 0; j < NEG_T; j++) {
            nsv[j] = neg_s[b * NEG_T + j];
            nrv[j] = neg_r[b * NEG_T + j];
        }
    }

    // ---- wait for fused kernel's results to be visible ----
    pdl_wait();

    float acc = 0.0f;

    // ---- wS * simi_mean gather: one k per thread ----
    if (tid < TOP_K)
        acc = fmaf(wsv, g_simi_mean[ix], acc);

    // ---- combine the 4 k-slice partials, compute std(ddof=1) dot w ----
    if (tid < EMB_V4) {
        float4 S = make_float4(0.f, 0.f, 0.f, 0.f);
        float4 Q = make_float4(0.f, 0.f, 0.f, 0.f);
        #pragma unroll
        for (int s = 0; s < KSLICES; s++) {
            int pb = (b << 2) + s;
            float4 ps = g_psum[pb * EMB_V4 + tid];
            float4 pq = g_psq [pb * EMB_V4 + tid];
            S.x += ps.x; S.y += ps.y; S.z += ps.z; S.w += ps.w;
            Q.x += pq.x; Q.y += pq.y; Q.z += pq.z; Q.w += pq.w;
        }
        const float invK  = 1.0f / (float)TOP_K;
        const float invK1 = 1.0f / (float)(TOP_K - 1);
        float ss[4] = {S.x, S.y, S.z, S.w};
        float qq[4] = {Q.x, Q.y, Q.z, Q.w};
        #pragma unroll
        for (int c = 0; c < 4; c++) {
            float mean = ss[c] * invK;
            float var  = fmaxf((qq[c] - ss[c] * mean) * invK1, 0.0f);
            acc = fmaf(sqrtf(var), wstd[c], acc);
        }
    }

    // ---- score-feature partials from k1 ----
    if (tid >= 1020) acc += g_sacc[(b << 2) + (tid - 1020)];

    float total = block_reduce_sum(acc, sh);

    // ---- sigmoid + this sample's loss contribution ----
    if (tid == 0) {
        float z = total + pb_bias;
        float a = 1.0f / (1.0f + __expf(-z));
        float pe = a * psv + (1.0f - a) * prv;
        float lsum = 0.0f;
        #pragma unroll
        for (int j = 0; j < NEG_T; j++) {
            float ne = a * nsv[j] + (1.0f - a) * nrv[j];
            lsum += fmaxf(MARGIN - pe + ne, 0.0f);
        }
        atomicAdd(out, lsum * (1.0f / (float)(BS * NEG_T)));
    }
}

// ---------------------------------------------------------------------------
extern "C" void kernel_launch(void* const* d_in, const int* in_sizes, int n_in,
                              void* d_out, int out_size) {
    const float* pos_stelp  = (const float*)d_in[0];
    const float* pos_rotate = (const float*)d_in[1];
    const int*   ent_idx    = (const int*)  d_in[2];
    const float* neg_stelp  = (const float*)d_in[3];
    const float* neg_rotate = (const float*)d_in[4];
    const float* stelp_sc   = (const float*)d_in[5];
    const float* rotate_sc  = (const float*)d_in[6];
    const float* ent_emb    = (const float*)d_in[7];
    const float* simi_mtx   = (const float*)d_in[8];
    const float* proj_w     = (const float*)d_in[9];
    const float* proj_b     = (const float*)d_in[10];
    float* out = (float*)d_out;

    fused_kernel<<<A_BLKS + N_ENT, 256>>>(simi_mtx, ent_idx, ent_emb,
                                          stelp_sc, rotate_sc, proj_w, out);

    // PDL secondary: launches while the fused grid drains; correctness is
    // enforced by griddepcontrol.wait inside the kernel.
    cudaLaunchConfig_t cfg = {};
    cfg.gridDim  = dim3(BS, 1, 1);
    cfg.blockDim = dim3(1024, 1, 1);
    cfg.dynamicSmemBytes = 0;
    cfg.stream = 0;
    cudaLaunchAttribute attrs[1];
    attrs[0].id = cudaLaunchAttributeProgrammaticStreamSerialization;
    attrs[0].val.programmaticStreamSerializationAllowed = 1;
    cfg.attrs = attrs;
    cfg.numAttrs = 1;
    cudaLaunchKernelEx(&cfg, phaseB_kernel,
                       ent_idx, proj_w, proj_b,
                       pos_stelp, pos_rotate, neg_stelp, neg_rotate, out);
}

// round 13
// speedup vs baseline: 1.0884x; 1.0138x over previous
#include <cuda_runtime.h>
#include <math.h>

#define N_ENT   14541
#define EMB_DIM 768
#define EMB_V4  192            // EMB_DIM / 4
#define TOP_K   1000
#define NEG_T   5
#define BS      128
#define MARGIN  0.5f

#define KSLICES 4
#define KSEG    (TOP_K / KSLICES)      // 250
#define A_BLKS  (BS * KSLICES)         // 512 alpha partial blocks

// Scratch (no cudaMalloc allowed)
__device__ float  g_simi_mean[N_ENT];
__device__ float4 g_psum[A_BLKS * EMB_V4];   // per (block, dim-group) partial sums
__device__ float4 g_psq [A_BLKS * EMB_V4];   // per (block, dim-group) partial sumsq
__device__ float  g_sacc[A_BLKS];            // per (b, slice) score-feature partial

// ---------------------------------------------------------------------------
// PDL primitives
// ---------------------------------------------------------------------------
__device__ __forceinline__ void pdl_trigger() {
    asm volatile("griddepcontrol.launch_dependents;");
}
__device__ __forceinline__ void pdl_wait() {
    asm volatile("griddepcontrol.wait;" ::: "memory");
}

// ---------------------------------------------------------------------------
// Block reduce: valid result in thread 0. Supports up to 1024 threads.
// ---------------------------------------------------------------------------
__device__ __forceinline__ float block_reduce_sum(float v, float* sh) {
    #pragma unroll
    for (int o = 16; o > 0; o >>= 1) v += __shfl_down_sync(0xffffffffu, v, o);
    int wid = threadIdx.x >> 5;
    int lid = threadIdx.x & 31;
    if (lid == 0) sh[wid] = v;
    __syncthreads();
    int nw = blockDim.x >> 5;
    if (wid == 0) {
        v = (lid < nw) ? sh[lid] : 0.0f;
        #pragma unroll
        for (int o = 16; o > 0; o >>= 1) v += __shfl_down_sync(0xffffffffu, v, o);
    }
    return v;
}

// ---------------------------------------------------------------------------
// Fused kernel 1 (alpha blocks FIRST as one short burst):
//   blocks [0, A_BLKS): alpha Phase A partials. Block (b, slice):
//       (1) gathers emb rows for its 250-k segment -> float4 sum/sumsq
//           partials (raw, no atomics, deterministic);
//       (2) computes the 4 row-mean-independent score-feature groups
//           (|r-s|, r+s, s, r) dotted with their weights -> g_sacc[bid].
//   blocks [A_BLKS, A_BLKS+N_ENT): per-row mean of simi_score_mtx
//       (DRAM-bound, __ldcs streaming so the emb table stays L2-resident).
// PDL trigger is the FIRST action of every block: the dependent grid launches
// when the last fused block STARTS (one block-duration of overlap), while
// griddepcontrol.wait in phaseB still enforces full visibility of all stores.
// ---------------------------------------------------------------------------
__global__ __launch_bounds__(256)
void fused_kernel(const float* __restrict__ simi,
                  const int*   __restrict__ ent_idx,
                  const float* __restrict__ emb,
                  const float* __restrict__ stelp_scores,
                  const float* __restrict__ rotate_scores,
                  const float* __restrict__ proj_w,
                  float* __restrict__ out) {
    __shared__ int   s_idx[KSEG];
    __shared__ float sh[8];
    const int tid = threadIdx.x;

    // First action: release the dependent-launch gate for this block.
    pdl_trigger();

    if (blockIdx.x < A_BLKS) {
        // ================= alpha Phase A partial =================
        const int b     = blockIdx.x >> 2;       // sample
        const int slice = blockIdx.x & 3;        // k-slice
        const int k0    = slice * KSEG;

        for (int k = tid; k < KSEG; k += 256)
            s_idx[k] = ent_idx[b * TOP_K + k0 + k];
        __syncthreads();

        // ---- score-feature partial (independent of row means) ----
        const float* wD  = proj_w + EMB_DIM + TOP_K;        // |rot - stelp|
        const float* wA  = proj_w + EMB_DIM + 2 * TOP_K;    // stelp + rot
        const float* wSt = proj_w + EMB_DIM + 3 * TOP_K;    // stelp
        const float* wR  = proj_w + EMB_DIM + 4 * TOP_K;    // rot
        float sacc = 0.0f;
        for (int k = tid; k < KSEG; k += 256) {
            const int kk = k0 + k;
            float ss = stelp_scores[b * TOP_K + kk];
            float rr = rotate_scores[b * TOP_K + kk];
            sacc = fmaf(wD[kk],  fabsf(rr - ss), sacc);
            sacc = fmaf(wA[kk],  ss + rr,        sacc);
            sacc = fmaf(wSt[kk], ss,             sacc);
            sacc = fmaf(wR[kk],  rr,             sacc);
        }

        // ---- emb gather: sum/sumsq per 4-dim group ----
        if (tid < EMB_V4) {
            // Thread tid owns dims [4*tid, 4*tid+4). A warp = 32 consecutive
            // float4s of the SAME row -> fully coalesced 512B bursts.
            const float4* __restrict__ emb4 = (const float4*)emb;
            float s0 = 0.f, s1 = 0.f, s2 = 0.f, s3 = 0.f;
            float q0 = 0.f, q1 = 0.f, q2 = 0.f, q3 = 0.f;
            #pragma unroll 10
            for (int k = 0; k < KSEG; k++) {
                float4 v = __ldg(emb4 + (size_t)s_idx[k] * EMB_V4 + tid);
                s0 += v.x; s1 += v.y; s2 += v.z; s3 += v.w;
                q0 = fmaf(v.x, v.x, q0); q1 = fmaf(v.y, v.y, q1);
                q2 = fmaf(v.z, v.z, q2); q3 = fmaf(v.w, v.w, q3);
            }
            g_psum[blockIdx.x * EMB_V4 + tid] = make_float4(s0, s1, s2, s3);
            g_psq [blockIdx.x * EMB_V4 + tid] = make_float4(q0, q1, q2, q3);
        }

        float stot = block_reduce_sum(sacc, sh);
        if (tid == 0) g_sacc[blockIdx.x] = stot;

    } else {
        // ================= row mean (streaming .cs loads) =================
        const int r = blockIdx.x - A_BLKS;
        if (r == 0 && tid == 0) out[0] = 0.0f;   // init for k2's atomic loss

        const size_t e0 = (size_t)r * N_ENT;
        const size_t e1 = e0 + N_ENT;
        const size_t a0 = (e0 + 3) & ~(size_t)3;   // first 16B-aligned element
        const size_t a1 = e1 & ~(size_t)3;

        float s = 0.0f;
        for (size_t e = e0 + tid; e < a0; e += 256) s += __ldcs(simi + e);
        for (size_t e = a1 + tid; e < e1; e += 256) s += __ldcs(simi + e);

        const float4* __restrict__ v4 = (const float4*)(simi + a0);
        const int nv = (int)((a1 - a0) >> 2);
        float4 a = make_float4(0.f, 0.f, 0.f, 0.f);
        #pragma unroll 4
        for (int i = tid; i < nv; i += 256) {
            float4 x = __ldcs(v4 + i);
            a.x += x.x; a.y += x.y; a.z += x.z; a.w += x.w;
        }
        s += (a.x + a.y) + (a.z + a.w);
        s = block_reduce_sum(s, sh);
        if (tid == 0) g_simi_mean[r] = s * (1.0f / (float)N_ENT);
    }
}

// ---------------------------------------------------------------------------
// Kernel 2 (PDL secondary): prologue loads everything independent of the
// fused kernel's outputs (overlapping the fused drain), then
// griddepcontrol.wait, then only the short L2-hot dependent part
// (simi_mean gather + partial combines + loss).
// One block of 1024 threads per sample, one k per thread.
// ---------------------------------------------------------------------------
__global__ __launch_bounds__(1024)
void phaseB_kernel(const int*   __restrict__ ent_idx,
                   const float* __restrict__ proj_w,
                   const float* __restrict__ proj_b,
                   const float* __restrict__ pos_s,
                   const float* __restrict__ pos_r,
                   const float* __restrict__ neg_s,
                   const float* __restrict__ neg_r,
                   float* __restrict__ out) {
    __shared__ float sh[32];
    const int b   = blockIdx.x;
    const int tid = threadIdx.x;

    // ---- prologue (overlaps with fused drain): input-only loads ----
    int   ix  = 0;
    float wsv = 0.0f;
    if (tid < TOP_K) {
        ix  = ent_idx[b * TOP_K + tid];
        wsv = __ldg(proj_w + EMB_DIM + tid);       // wS[tid]
    }
    float wstd[4] = {0.f, 0.f, 0.f, 0.f};
    if (tid < EMB_V4) {
        #pragma unroll
        for (int c = 0; c < 4; c++) wstd[c] = __ldg(proj_w + 4 * tid + c);
    }
    float pb_bias = (tid == 0) ? __ldg(proj_b) : 0.0f;
    float psv = 0.f, prv = 0.f, nsv[NEG_T], nrv[NEG_T];
    if (tid == 0) {
        psv = pos_s[b]; prv = pos_r[b];
        #pragma unroll
        for (int j = 0; j < NEG_T; j++) {
            nsv[j] = neg_s[b * NEG_T + j];
            nrv[j] = neg_r[b * NEG_T + j];
        }
    }

    // ---- wait for fused kernel's results to be visible ----
    pdl_wait();

    float acc = 0.0f;

    // ---- wS * simi_mean gather: one k per thread ----
    if (tid < TOP_K)
        acc = fmaf(wsv, g_simi_mean[ix], acc);

    // ---- combine the 4 k-slice partials, compute std(ddof=1) dot w ----
    if (tid < EMB_V4) {
        float4 S = make_float4(0.f, 0.f, 0.f, 0.f);
        float4 Q = make_float4(0.f, 0.f, 0.f, 0.f);
        #pragma unroll
        for (int s = 0; s < KSLICES; s++) {
            int pb = (b << 2) + s;
            float4 ps = g_psum[pb * EMB_V4 + tid];
            float4 pq = g_psq [pb * EMB_V4 + tid];
            S.x += ps.x; S.y += ps.y; S.z += ps.z; S.w += ps.w;
            Q.x += pq.x; Q.y += pq.y; Q.z += pq.z; Q.w += pq.w;
        }
        const float invK  = 1.0f / (float)TOP_K;
        const float invK1 = 1.0f / (float)(TOP_K - 1);
        float ss[4] = {S.x, S.y, S.z, S.w};
        float qq[4] = {Q.x, Q.y, Q.z, Q.w};
        #pragma unroll
        for (int c = 0; c < 4; c++) {
            float mean = ss[c] * invK;
            float var  = fmaxf((qq[c] - ss[c] * mean) * invK1, 0.0f);
            acc = fmaf(sqrtf(var), wstd[c], acc);
        }
    }

    // ---- score-feature partials from k1 ----
    if (tid >= 1020) acc += g_sacc[(b << 2) + (tid - 1020)];

    float total = block_reduce_sum(acc, sh);

    // ---- sigmoid + this sample's loss contribution ----
    if (tid == 0) {
        float z = total + pb_bias;
        float a = 1.0f / (1.0f + __expf(-z));
        float pe = a * psv + (1.0f - a) * prv;
        float lsum = 0.0f;
        #pragma unroll
        for (int j = 0; j < NEG_T; j++) {
            float ne = a * nsv[j] + (1.0f - a) * nrv[j];
            lsum += fmaxf(MARGIN - pe + ne, 0.0f);
        }
        atomicAdd(out, lsum * (1.0f / (float)(BS * NEG_T)));
    }
}

// ---------------------------------------------------------------------------
extern "C" void kernel_launch(void* const* d_in, const int* in_sizes, int n_in,
                              void* d_out, int out_size) {
    const float* pos_stelp  = (const float*)d_in[0];
    const float* pos_rotate = (const float*)d_in[1];
    const int*   ent_idx    = (const int*)  d_in[2];
    const float* neg_stelp  = (const float*)d_in[3];
    const float* neg_rotate = (const float*)d_in[4];
    const float* stelp_sc   = (const float*)d_in[5];
    const float* rotate_sc  = (const float*)d_in[6];
    const float* ent_emb    = (const float*)d_in[7];
    const float* simi_mtx   = (const float*)d_in[8];
    const float* proj_w     = (const float*)d_in[9];
    const float* proj_b     = (const float*)d_in[10];
    float* out = (float*)d_out;

    fused_kernel<<<A_BLKS + N_ENT, 256>>>(simi_mtx, ent_idx, ent_emb,
                                          stelp_sc, rotate_sc, proj_w, out);

    // PDL secondary: launches while the fused grid drains; correctness is
    // enforced by griddepcontrol.wait inside the kernel.
    cudaLaunchConfig_t cfg = {};
    cfg.gridDim  = dim3(BS, 1, 1);
    cfg.blockDim = dim3(1024, 1, 1);
    cfg.dynamicSmemBytes = 0;
    cfg.stream = 0;
    cudaLaunchAttribute attrs[1];
    attrs[0].id = cudaLaunchAttributeProgrammaticStreamSerialization;
    attrs[0].val.programmaticStreamSerializationAllowed = 1;
    cfg.attrs = attrs;
    cfg.numAttrs = 1;
    cudaLaunchKernelEx(&cfg, phaseB_kernel,
                       ent_idx, proj_w, proj_b,
                       pos_stelp, pos_rotate, neg_stelp, neg_rotate, out);
}